// round 14
// baseline (speedup 1.0000x reference)
#include <cuda_runtime.h>
#include <cuda_bf16.h>
#include <math.h>

#define B_ 128
#define T_ 1024
#define D_ 128
#define U_ 256
#define M_ 64

// Static device scratch (no cudaMalloc anywhere)
// Layout: [t][bg(16)][sl(8)][g(4)][b(8)][c(32)]  (CTA-contiguous blocks)
__device__ float g_X[134217728];

// ---------------------------------------------------------------------------
// helpers
// ---------------------------------------------------------------------------
__device__ __forceinline__ void fma2(unsigned long long& d,
                                     unsigned long long a,
                                     unsigned long long b) {
    asm("fma.rn.f32x2 %0, %1, %2, %0;" : "+l"(d) : "l"(a), "l"(b));
}
__device__ __forceinline__ float sum2(unsigned long long v) {
    return __uint_as_float((unsigned)v) + __uint_as_float((unsigned)(v >> 32));
}
__device__ __forceinline__ unsigned long long pk2(float a, float b) {
    unsigned long long r;
    asm("mov.b64 %0, {%1, %2};" : "=l"(r) : "f"(a), "f"(b));
    return r;
}
__device__ __forceinline__ unsigned smu32(const void* p) {
    return (unsigned)__cvta_generic_to_shared(p);
}
__device__ __forceinline__ void mb_init(unsigned mbar, unsigned count) {
    asm volatile("mbarrier.init.shared.b64 [%0], %1;"
                 :: "r"(mbar), "r"(count) : "memory");
}
__device__ __forceinline__ void mb_expect_tx(unsigned mbar, unsigned bytes) {
    asm volatile("mbarrier.arrive.expect_tx.shared.b64 _, [%0], %1;"
                 :: "r"(mbar), "r"(bytes) : "memory");
}
__device__ __forceinline__ void mb_wait(unsigned mbar, unsigned parity) {
    unsigned done;
    asm volatile(
        "{\n\t.reg .pred p;\n\t"
        "mbarrier.try_wait.parity.acquire.cta.shared::cta.b64 p, [%1], %2;\n\t"
        "selp.b32 %0, 1, 0, p;\n\t}"
        : "=r"(done) : "r"(mbar), "r"(parity) : "memory");
    while (!done) {
        asm volatile(
            "{\n\t.reg .pred p;\n\t"
            "mbarrier.try_wait.parity.acquire.cta.shared::cta.b64 p, [%1], %2, 0x989680;\n\t"
            "selp.b32 %0, 1, 0, p;\n\t}"
            : "=r"(done) : "r"(mbar), "r"(parity) : "memory");
    }
}
#define LDSM4(r0, r1, r2, r3, a) \
    asm volatile("ldmatrix.sync.aligned.m8n8.x4.shared.b16 {%0,%1,%2,%3}, [%4];" \
                 : "=r"(r0), "=r"(r1), "=r"(r2), "=r"(r3) : "r"(a))
#define LDSM2(r0, r1, a) \
    asm volatile("ldmatrix.sync.aligned.m8n8.x2.shared.b16 {%0,%1}, [%2];" \
                 : "=r"(r0), "=r"(r1) : "r"(a))
#define MMA16816(d0, d1, d2, d3, a0, a1, a2, a3, b0, b1) \
    asm volatile("mma.sync.aligned.m16n8k16.row.col.f32.bf16.bf16.f32 " \
                 "{%0,%1,%2,%3}, {%4,%5,%6,%7}, {%8,%9}, {%0,%1,%2,%3};" \
                 : "+f"(d0), "+f"(d1), "+f"(d2), "+f"(d3) \
                 : "r"(a0), "r"(a1), "r"(a2), "r"(a3), "r"(b0), "r"(b1))

// ---------------------------------------------------------------------------
// K1: input projections (R11 version — known-good)
// ---------------------------------------------------------------------------
#define P_ISH_STR 130
#define P_WSH_STR 68
#define P_WSH_OFF (128 * P_ISH_STR)
#define P_WBUF    (128 * P_WSH_STR)
#define K1_SMEM_BYTES ((128 * P_ISH_STR + 2 * P_WBUF) * 4)

__global__ void __launch_bounds__(512) proj_kernel(
    const float* __restrict__ inp,
    const float* __restrict__ Wi, const float* __restrict__ Wf,
    const float* __restrict__ Wc, const float* __restrict__ Wo,
    const float* __restrict__ bi, const float* __restrict__ bf,
    const float* __restrict__ bc, const float* __restrict__ bo)
{
    extern __shared__ float sm[];
    float* Ish = sm;
    float* Wsh = sm + P_WSH_OFF;

    const int t   = blockIdx.x;
    const int tid = threadIdx.x;

    const float* Wmat[4] = { Wi, Wf, Wc, Wo };
    const float* bvec[4] = { bi, bf, bc, bo };

    for (int i = tid; i < 128 * 128; i += 512) {
        int b = i >> 7, d = i & 127;
        Ish[b * P_ISH_STR + d] = inp[((size_t)b * T_ + t) * D_ + d];
    }
    {
        const float* W = Wmat[0];
#pragma unroll
        for (int k = 0; k < 4; k++) {
            int fi = tid + 512 * k;
            int d  = fi >> 4, u4 = fi & 15;
            *(float4*)&Wsh[d * P_WSH_STR + u4 * 4] =
                *(const float4*)&W[(size_t)d * U_ + u4 * 4];
        }
    }
    __syncthreads();

    const int j4 = (tid & 15) * 4;
    const int b4 = (tid >> 4) * 4;

    for (int tl = 0; tl < 16; tl++) {
        const int g  = tl >> 2;
        const int u0 = (tl & 3) * 64;
        float* Wcur = Wsh + (tl & 1) * P_WBUF;

        float4 wpre[4];
        if (tl + 1 < 16) {
            const float* W = Wmat[(tl + 1) >> 2];
            const int nu0 = ((tl + 1) & 3) * 64;
#pragma unroll
            for (int k = 0; k < 4; k++) {
                int fi = tid + 512 * k;
                int d  = fi >> 4, u4 = fi & 15;
                wpre[k] = *(const float4*)&W[(size_t)d * U_ + nu0 + u4 * 4];
            }
        }

        unsigned long long acc[4][4];
#pragma unroll
        for (int jj = 0; jj < 4; jj++)
#pragma unroll
            for (int bb = 0; bb < 4; bb++) acc[jj][bb] = 0ull;

#pragma unroll 8
        for (int d = 0; d < 128; d += 2) {
            float4 wa = *(const float4*)&Wcur[d * P_WSH_STR + j4];
            float4 wb = *(const float4*)&Wcur[(d + 1) * P_WSH_STR + j4];
            unsigned long long w0 = pk2(wa.x, wb.x), w1 = pk2(wa.y, wb.y);
            unsigned long long w2 = pk2(wa.z, wb.z), w3 = pk2(wa.w, wb.w);
#pragma unroll
            for (int bb = 0; bb < 4; bb++) {
                unsigned long long iv = *(const unsigned long long*)
                    &Ish[(b4 + bb) * P_ISH_STR + d];
                fma2(acc[0][bb], w0, iv);
                fma2(acc[1][bb], w1, iv);
                fma2(acc[2][bb], w2, iv);
                fma2(acc[3][bb], w3, iv);
            }
        }

        const int u   = u0 + j4;
        const int slo = u >> 5;
        const int co  = u & 31;
        const float bv0 = bvec[g][u + 0], bv1 = bvec[g][u + 1];
        const float bv2 = bvec[g][u + 2], bv3 = bvec[g][u + 3];
#pragma unroll
        for (int bb = 0; bb < 4; bb++) {
            int bfull = b4 + bb;
            float* p = g_X + (size_t)t * 131072 + (size_t)(bfull >> 3) * 8192 +
                       slo * 1024 + g * 256 + (bfull & 7) * 32 + co;
            *(float4*)p = make_float4(sum2(acc[0][bb]) + bv0,
                                      sum2(acc[1][bb]) + bv1,
                                      sum2(acc[2][bb]) + bv2,
                                      sum2(acc[3][bb]) + bv3);
        }

        if (tl + 1 < 16) {
            float* Wnxt = Wsh + ((tl + 1) & 1) * P_WBUF;
#pragma unroll
            for (int k = 0; k < 4; k++) {
                int fi = tid + 512 * k;
                int d  = fi >> 4, u4 = fi & 15;
                *(float4*)&Wnxt[d * P_WSH_STR + u4 * 4] = wpre[k];
            }
            __syncthreads();
        }
    }
}

// ---------------------------------------------------------------------------
// K2: persistent recurrence, cluster-8, 640 threads (20 warps), HMMA.
// D[160 m][8 b] = A[160][256] @ h[8][256]^T, split-bf16 3-term.
//   m 0..127: gates (g = m>>5, c = m&31 of this CTA's 32-col slice)
//   m 128..159: Cmem rows (mem_read); r accumulated fp32 in gate threads.
// Warp w (0..19): m-tile = (w>>1)*16, K-half = (w&1)*128. A fragments
// register-resident (loaded once). Per step: 16 ldmatrix.x2 (B) + 24 HMMA.
// Comm: R10 bulk-DSMEM + xch mbar. Pusher/x-stager = warp 19.
// ---------------------------------------------------------------------------
#define A_OFF    0                          // [2 term][160 m][264 k] bf16
#define A_TERM   84480                      // 160*528
#define BT_OFF   168960                     // [2 par][2 term][8 n][264 k] bf16
#define BT_PAR   8448
#define BT_TERM  4224
#define STG_OFF  185856                     // [2 par][8 src][8 b][32 k] f32
#define ZB_OFF   202240                     // [2 kh][160 m][9] f32
#define XB_OFF   213760                     // [2 par][1024] f32
#define HST_OFF  221952                     // [2 par][256] f32
#define MB_OFF   224000                     // xch mbar
#define R_SMEM_BYTES 224032

__global__ void __launch_bounds__(640, 1) __cluster_dims__(8, 1, 1)
recur_kernel(const float* __restrict__ Ui, const float* __restrict__ Uf,
             const float* __restrict__ Uc, const float* __restrict__ Uo,
             const float* __restrict__ Wmem, const float* __restrict__ Umem,
             float* __restrict__ out)
{
    extern __shared__ char smc[];
    const int bg   = blockIdx.x >> 3;
    const int sl   = blockIdx.x & 7;
    const int tid  = threadIdx.x;
    const int warp = tid >> 5;
    const int lane = tid & 31;

    const unsigned smb    = smu32(smc);
    const unsigned xch_mb = smb + MB_OFF;

    float* stg  = (float*)(smc + STG_OFF);
    float* zb   = (float*)(smc + ZB_OFF);
    float* xb   = (float*)(smc + XB_OFF);
    float* hst  = (float*)(smc + HST_OFF);

    if (tid == 0) mb_init(xch_mb, 1);

    // ---- fill A (hi/lo bf16): gates then Cmem ----
    for (int idx = tid; idx < 32768; idx += 640) {
        int m = idx >> 8, k = idx & 255;
        int g = m >> 5;
        const float* W = (g == 0) ? Ui : (g == 1) ? Uf : (g == 2) ? Uc : Uo;
        float w = W[(size_t)k * U_ + sl * 32 + (m & 31)];
        __nv_bfloat16 h1 = __float2bfloat16(w);
        __nv_bfloat16 h2 = __float2bfloat16(w - __bfloat162float(h1));
        *(__nv_bfloat16*)(smc + A_OFF + m * 528 + k * 2) = h1;
        *(__nv_bfloat16*)(smc + A_OFF + A_TERM + m * 528 + k * 2) = h2;
    }
    for (int idx = tid; idx < 8192; idx += 640) {
        int c = idx >> 8, k = idx & 255;
        float s = 0.f;
#pragma unroll 8
        for (int m2 = 0; m2 < M_; m2++)
            s += Umem[k * M_ + m2] * Wmem[m2 * U_ + sl * 32 + c];
        float w = 0.1f * s;
        int m = 128 + c;
        __nv_bfloat16 h1 = __float2bfloat16(w);
        __nv_bfloat16 h2 = __float2bfloat16(w - __bfloat162float(h1));
        *(__nv_bfloat16*)(smc + A_OFF + m * 528 + k * 2) = h1;
        *(__nv_bfloat16*)(smc + A_OFF + A_TERM + m * 528 + k * 2) = h2;
    }
    for (int i = tid; i < 4096; i += 640) stg[i] = 0.f;     // h(-1) = 0
    for (int i = tid; i < 1024; i += 640)                    // x for t = 0
        xb[i] = g_X[(size_t)bg * 8192 + sl * 1024 + i];

    // pusher (warp 19) peer addresses
    unsigned rd_base = 0, rm_peer = 0;
    if (warp == 19 && lane < 8) {
        asm("mapa.shared::cluster.u32 %0, %1, %2;" : "=r"(rd_base)
            : "r"(smb + STG_OFF + (unsigned)(sl * 1024)), "r"(lane));
        asm("mapa.shared::cluster.u32 %0, %1, %2;" : "=r"(rm_peer)
            : "r"(xch_mb), "r"(lane));
    }
    __syncthreads();

    // ---- load A fragments into registers (once) ----
    const int tau = warp >> 1;               // m-tile 0..9
    const int kh  = warp & 1;                // K-half
    const unsigned arow = (unsigned)((lane & 7) + ((lane >> 3) & 1) * 8);
    const unsigned acol = (unsigned)((lane >> 4) * 8);
    const unsigned aAddrH = smb + A_OFF + (tau * 16 + arow) * 528 +
                            (kh * 128 + acol) * 2;
    const unsigned aAddrL = aAddrH + A_TERM;
    unsigned aH[8][4], aL[8][4];
#pragma unroll
    for (int q = 0; q < 8; q++) {
        LDSM4(aH[q][0], aH[q][1], aH[q][2], aH[q][3], aAddrH + q * 32);
        LDSM4(aL[q][0], aL[q][1], aL[q][2], aL[q][3], aAddrL + q * 32);
    }

    // B ldmatrix lane base (x2 uses lanes 0..15; replicate pattern above)
    const unsigned l2   = (unsigned)(lane & 15);
    const unsigned bBase = smb + BT_OFF + (l2 & 7) * 528 +
                           (((l2 >> 3) & 1) * 8 + kh * 128) * 2;

    // gate-thread persistent state (tid < 256)
    const int gb  = tid >> 5;
    const int gcc = tid & 31;
    float creg = 0.f, rreg = 0.f;
    float* outp = out + ((size_t)(bg * 8 + gb) * T_) * U_ + sl * 32 + gcc;

    if (tid == 0) mb_expect_tx(xch_mb, 8192);    // phase 0 (consumed at t=1)
    __syncthreads();
    asm volatile("barrier.cluster.arrive.aligned;" ::: "memory");
    asm volatile("barrier.cluster.wait.aligned;" ::: "memory");

    for (int t = 0; t < T_; t++) {
        const int cur = t & 1, nxt = cur ^ 1;

        // ---- (a) wait for exchanged h (phase t-1), repost expect ----
        if (t > 0) {
            mb_wait(xch_mb, (unsigned)((t - 1) & 1));
            if (tid == 0) mb_expect_tx(xch_mb, 8192);
        }

        // ---- (b) build B tiles (bf16 hi/lo) from staged fp32 h ----
        if (tid < 512) {
            const float* sc = stg + cur * 2048;
            char* bt = smc + BT_OFF + cur * BT_PAR;
#pragma unroll
            for (int r = 0; r < 2; r++) {
                int w2 = tid * 2 + r;        // word 0..1023
                int b  = w2 >> 7;
                int k  = (w2 & 127) * 2;
                int q  = k >> 5, kk = k & 31;
                float v0 = sc[q * 256 + b * 32 + kk];
                float v1 = sc[q * 256 + b * 32 + kk + 1];
                __nv_bfloat16 h0 = __float2bfloat16(v0);
                __nv_bfloat16 l0 = __float2bfloat16(v0 - __bfloat162float(h0));
                __nv_bfloat16 h1 = __float2bfloat16(v1);
                __nv_bfloat16 l1 = __float2bfloat16(v1 - __bfloat162float(h1));
                unsigned hiw = (unsigned)__bfloat16_as_ushort(h0) |
                               ((unsigned)__bfloat16_as_ushort(h1) << 16);
                unsigned low = (unsigned)__bfloat16_as_ushort(l0) |
                               ((unsigned)__bfloat16_as_ushort(l1) << 16);
                *(unsigned*)(bt + b * 528 + k * 2)           = hiw;
                *(unsigned*)(bt + BT_TERM + b * 528 + k * 2) = low;
            }
        }
        __syncthreads();                     // (c)

        // ---- (d) MMA: 8 ksteps x 3 terms ----
        {
            float d0 = 0.f, d1 = 0.f, d2 = 0.f, d3 = 0.f;
            const unsigned bp = bBase + (unsigned)(cur * BT_PAR);
#pragma unroll
            for (int q = 0; q < 8; q++) {
                unsigned bh0, bh1, bl0, bl1;
                LDSM2(bh0, bh1, bp + q * 32);
                LDSM2(bl0, bl1, bp + BT_TERM + q * 32);
                MMA16816(d0, d1, d2, d3, aH[q][0], aH[q][1], aH[q][2],
                         aH[q][3], bh0, bh1);
                MMA16816(d0, d1, d2, d3, aH[q][0], aH[q][1], aH[q][2],
                         aH[q][3], bl0, bl1);
                MMA16816(d0, d1, d2, d3, aL[q][0], aL[q][1], aL[q][2],
                         aL[q][3], bh0, bh1);
            }
            // store D to zbuf: rows tau*16 + lane/4 (+8), cols (lane&3)*2
            const int m0 = tau * 16 + (lane >> 2);
            const int n0 = (lane & 3) * 2;
            float* zr_ = zb + kh * 1440;
            zr_[m0 * 9 + n0]       = d0;
            zr_[m0 * 9 + n0 + 1]   = d1;
            zr_[(m0 + 8) * 9 + n0]     = d2;
            zr_[(m0 + 8) * 9 + n0 + 1] = d3;
        }
        __syncthreads();                     // (e) zbuf ready

        // ---- (f) gates (tid<256) ; warp 19 stages x and pushes ----
        if (tid < 256) {
            const float* z0 = zb;
            const float* z1 = zb + 1440;
            float zi = z0[gcc * 9 + gb]         + z1[gcc * 9 + gb];
            float zf = z0[(32 + gcc) * 9 + gb]  + z1[(32 + gcc) * 9 + gb];
            float zc = z0[(64 + gcc) * 9 + gb]  + z1[(64 + gcc) * 9 + gb];
            float zo = z0[(96 + gcc) * 9 + gb]  + z1[(96 + gcc) * 9 + gb];
            float zr = z0[(128 + gcc) * 9 + gb] + z1[(128 + gcc) * 9 + gb];
            const float* xc = xb + cur * 1024 + tid;
            float rn = rreg + zr;
            float pi  = xc[0]   + zi + rn;
            float pff = xc[256] + zf;
            float pc  = xc[512] + zc;
            float po  = xc[768] + zo;
            float ig = __fdividef(1.f, 1.f + __expf(-pi));
            float fg = __fdividef(1.f, 1.f + __expf(-pff));
            float ct = __fdividef(2.f, 1.f + __expf(-2.f * pc)) - 1.f;
            float og = __fdividef(1.f, 1.f + __expf(-po));
            float cn = fg * creg + ig * ct;
            float hv = og * (__fdividef(2.f, 1.f + __expf(-2.f * cn)) - 1.f);
            creg = cn;
            rreg = rn;
            hst[cur * 256 + tid] = hv;

            asm volatile("bar.sync 2, 288;" ::: "memory");
            outp[(size_t)t * U_] = hv;
        } else if (warp == 19) {
            // stage x_{t+1} into xb[nxt] (latency hidden vs gates)
            if (t + 1 < T_) {
                const float4* src = (const float4*)(g_X +
                    (size_t)(t + 1) * 131072 + bg * 8192 + sl * 1024);
                float4* dstx = (float4*)(xb + nxt * 1024);
#pragma unroll
                for (int i = 0; i < 8; i++)
                    dstx[lane + 32 * i] = src[lane + 32 * i];
            }
            asm volatile("bar.sync 2, 288;" ::: "memory");
            if (lane < 8 && t + 1 < T_) {
                asm volatile("fence.proxy.async.shared::cta;" ::: "memory");
                unsigned dst = rd_base + (unsigned)(nxt * 8192);
                unsigned src = smb + HST_OFF + (unsigned)(cur * 1024);
                asm volatile(
                    "cp.async.bulk.shared::cluster.shared::cta"
                    ".mbarrier::complete_tx::bytes [%0], [%1], %2, [%3];"
                    :: "r"(dst), "r"(src), "r"(1024u), "r"(rm_peer)
                    : "memory");
            }
        }
        // warps 8..18 proceed to next iteration (protected by the xch
        // dataflow: phase t completes only after all 8 CTAs' pushes, each
        // of which follows that CTA's bar 2 => all zbuf/BT reads done).
    }

    asm volatile("barrier.cluster.arrive.aligned;" ::: "memory");
    asm volatile("barrier.cluster.wait.aligned;" ::: "memory");
}

// ---------------------------------------------------------------------------
// Launcher: capture-legal (exactly 2 kernel launches, default stream)
// ---------------------------------------------------------------------------
extern "C" void kernel_launch(void* const* d_in, const int* in_sizes, int n_in,
                              void* d_out, int out_size)
{
    const float* inp  = (const float*)d_in[0];
    const float* Wi   = (const float*)d_in[1];
    const float* Wf   = (const float*)d_in[2];
    const float* Wc   = (const float*)d_in[3];
    const float* Wo   = (const float*)d_in[4];
    const float* Uig  = (const float*)d_in[5];
    const float* Ufg  = (const float*)d_in[6];
    const float* Ucg  = (const float*)d_in[7];
    const float* Uog  = (const float*)d_in[8];
    const float* Wmem = (const float*)d_in[9];
    const float* Umem = (const float*)d_in[10];
    const float* bi   = (const float*)d_in[11];
    const float* bf   = (const float*)d_in[12];
    const float* bc   = (const float*)d_in[13];
    const float* bo   = (const float*)d_in[14];
    float* out = (float*)d_out;

    cudaFuncSetAttribute(proj_kernel,
                         cudaFuncAttributeMaxDynamicSharedMemorySize,
                         K1_SMEM_BYTES);
    proj_kernel<<<1024, 512, K1_SMEM_BYTES, 0>>>(inp, Wi, Wf, Wc, Wo,
                                                 bi, bf, bc, bo);

    cudaFuncSetAttribute(recur_kernel,
                         cudaFuncAttributeMaxDynamicSharedMemorySize,
                         R_SMEM_BYTES);
    recur_kernel<<<128, 640, R_SMEM_BYTES, 0>>>(Uig, Ufg, Ucg, Uog,
                                                Wmem, Umem, out);
}

// round 15
// speedup vs baseline: 1.5313x; 1.5313x over previous
#include <cuda_runtime.h>
#include <cuda_bf16.h>
#include <math.h>

#define B_ 128
#define T_ 1024
#define D_ 128
#define U_ 256
#define M_ 64

// Static device scratch (no cudaMalloc anywhere)
// Layout: [t][bg(16)][sl(8)][g(4)][b(8)][c(32)]  (CTA-contiguous blocks)
__device__ float g_X[134217728];

// ---------------------------------------------------------------------------
// helpers
// ---------------------------------------------------------------------------
__device__ __forceinline__ void fma2(unsigned long long& d,
                                     unsigned long long a,
                                     unsigned long long b) {
    asm("fma.rn.f32x2 %0, %1, %2, %0;" : "+l"(d) : "l"(a), "l"(b));
}
__device__ __forceinline__ float sum2(unsigned long long v) {
    return __uint_as_float((unsigned)v) + __uint_as_float((unsigned)(v >> 32));
}
__device__ __forceinline__ unsigned long long pk2(float a, float b) {
    unsigned long long r;
    asm("mov.b64 %0, {%1, %2};" : "=l"(r) : "f"(a), "f"(b));
    return r;
}
__device__ __forceinline__ unsigned smu32(const void* p) {
    return (unsigned)__cvta_generic_to_shared(p);
}
__device__ __forceinline__ void mb_init(unsigned mbar, unsigned count) {
    asm volatile("mbarrier.init.shared.b64 [%0], %1;"
                 :: "r"(mbar), "r"(count) : "memory");
}
__device__ __forceinline__ void mb_expect_tx(unsigned mbar, unsigned bytes) {
    asm volatile("mbarrier.arrive.expect_tx.shared.b64 _, [%0], %1;"
                 :: "r"(mbar), "r"(bytes) : "memory");
}
__device__ __forceinline__ void mb_wait(unsigned mbar, unsigned parity) {
    unsigned done;
    asm volatile(
        "{\n\t.reg .pred p;\n\t"
        "mbarrier.try_wait.parity.acquire.cta.shared::cta.b64 p, [%1], %2;\n\t"
        "selp.b32 %0, 1, 0, p;\n\t}"
        : "=r"(done) : "r"(mbar), "r"(parity) : "memory");
    while (!done) {
        asm volatile(
            "{\n\t.reg .pred p;\n\t"
            "mbarrier.try_wait.parity.acquire.cta.shared::cta.b64 p, [%1], %2, 0x989680;\n\t"
            "selp.b32 %0, 1, 0, p;\n\t}"
            : "=r"(done) : "r"(mbar), "r"(parity) : "memory");
    }
}
#define LDSM4(r0, r1, r2, r3, a) \
    asm volatile("ldmatrix.sync.aligned.m8n8.x4.shared.b16 {%0,%1,%2,%3}, [%4];" \
                 : "=r"(r0), "=r"(r1), "=r"(r2), "=r"(r3) : "r"(a))
#define LDSM2(r0, r1, a) \
    asm volatile("ldmatrix.sync.aligned.m8n8.x2.shared.b16 {%0,%1}, [%2];" \
                 : "=r"(r0), "=r"(r1) : "r"(a))
#define MMA16816(d0, d1, d2, d3, a0, a1, a2, a3, b0, b1) \
    asm volatile("mma.sync.aligned.m16n8k16.row.col.f32.bf16.bf16.f32 " \
                 "{%0,%1,%2,%3}, {%4,%5,%6,%7}, {%8,%9}, {%0,%1,%2,%3};" \
                 : "+f"(d0), "+f"(d1), "+f"(d2), "+f"(d3) \
                 : "r"(a0), "r"(a1), "r"(a2), "r"(a3), "r"(b0), "r"(b1))
#define CP_ASYNC4(dst, src) \
    asm volatile("cp.async.ca.shared.global [%0], [%1], 4;" \
                 :: "r"(dst), "l"(src) : "memory")
#define CP_COMMIT() asm volatile("cp.async.commit_group;" ::: "memory")
#define CP_WAIT1()  asm volatile("cp.async.wait_group 1;" ::: "memory")

// ---------------------------------------------------------------------------
// K1: input projections (R11 version — known-good)
// ---------------------------------------------------------------------------
#define P_ISH_STR 130
#define P_WSH_STR 68
#define P_WSH_OFF (128 * P_ISH_STR)
#define P_WBUF    (128 * P_WSH_STR)
#define K1_SMEM_BYTES ((128 * P_ISH_STR + 2 * P_WBUF) * 4)

__global__ void __launch_bounds__(512) proj_kernel(
    const float* __restrict__ inp,
    const float* __restrict__ Wi, const float* __restrict__ Wf,
    const float* __restrict__ Wc, const float* __restrict__ Wo,
    const float* __restrict__ bi, const float* __restrict__ bf,
    const float* __restrict__ bc, const float* __restrict__ bo)
{
    extern __shared__ float sm[];
    float* Ish = sm;
    float* Wsh = sm + P_WSH_OFF;

    const int t   = blockIdx.x;
    const int tid = threadIdx.x;

    const float* Wmat[4] = { Wi, Wf, Wc, Wo };
    const float* bvec[4] = { bi, bf, bc, bo };

    for (int i = tid; i < 128 * 128; i += 512) {
        int b = i >> 7, d = i & 127;
        Ish[b * P_ISH_STR + d] = inp[((size_t)b * T_ + t) * D_ + d];
    }
    {
        const float* W = Wmat[0];
#pragma unroll
        for (int k = 0; k < 4; k++) {
            int fi = tid + 512 * k;
            int d  = fi >> 4, u4 = fi & 15;
            *(float4*)&Wsh[d * P_WSH_STR + u4 * 4] =
                *(const float4*)&W[(size_t)d * U_ + u4 * 4];
        }
    }
    __syncthreads();

    const int j4 = (tid & 15) * 4;
    const int b4 = (tid >> 4) * 4;

    for (int tl = 0; tl < 16; tl++) {
        const int g  = tl >> 2;
        const int u0 = (tl & 3) * 64;
        float* Wcur = Wsh + (tl & 1) * P_WBUF;

        float4 wpre[4];
        if (tl + 1 < 16) {
            const float* W = Wmat[(tl + 1) >> 2];
            const int nu0 = ((tl + 1) & 3) * 64;
#pragma unroll
            for (int k = 0; k < 4; k++) {
                int fi = tid + 512 * k;
                int d  = fi >> 4, u4 = fi & 15;
                wpre[k] = *(const float4*)&W[(size_t)d * U_ + nu0 + u4 * 4];
            }
        }

        unsigned long long acc[4][4];
#pragma unroll
        for (int jj = 0; jj < 4; jj++)
#pragma unroll
            for (int bb = 0; bb < 4; bb++) acc[jj][bb] = 0ull;

#pragma unroll 8
        for (int d = 0; d < 128; d += 2) {
            float4 wa = *(const float4*)&Wcur[d * P_WSH_STR + j4];
            float4 wb = *(const float4*)&Wcur[(d + 1) * P_WSH_STR + j4];
            unsigned long long w0 = pk2(wa.x, wb.x), w1 = pk2(wa.y, wb.y);
            unsigned long long w2 = pk2(wa.z, wb.z), w3 = pk2(wa.w, wb.w);
#pragma unroll
            for (int bb = 0; bb < 4; bb++) {
                unsigned long long iv = *(const unsigned long long*)
                    &Ish[(b4 + bb) * P_ISH_STR + d];
                fma2(acc[0][bb], w0, iv);
                fma2(acc[1][bb], w1, iv);
                fma2(acc[2][bb], w2, iv);
                fma2(acc[3][bb], w3, iv);
            }
        }

        const int u   = u0 + j4;
        const int slo = u >> 5;
        const int co  = u & 31;
        const float bv0 = bvec[g][u + 0], bv1 = bvec[g][u + 1];
        const float bv2 = bvec[g][u + 2], bv3 = bvec[g][u + 3];
#pragma unroll
        for (int bb = 0; bb < 4; bb++) {
            int bfull = b4 + bb;
            float* p = g_X + (size_t)t * 131072 + (size_t)(bfull >> 3) * 8192 +
                       slo * 1024 + g * 256 + (bfull & 7) * 32 + co;
            *(float4*)p = make_float4(sum2(acc[0][bb]) + bv0,
                                      sum2(acc[1][bb]) + bv1,
                                      sum2(acc[2][bb]) + bv2,
                                      sum2(acc[3][bb]) + bv3);
        }

        if (tl + 1 < 16) {
            float* Wnxt = Wsh + ((tl + 1) & 1) * P_WBUF;
#pragma unroll
            for (int k = 0; k < 4; k++) {
                int fi = tid + 512 * k;
                int d  = fi >> 4, u4 = fi & 15;
                *(float4*)&Wnxt[d * P_WSH_STR + u4 * 4] = wpre[k];
            }
            __syncthreads();
        }
    }
}

// ---------------------------------------------------------------------------
// K2: persistent recurrence, cluster-8, 640 threads, HMMA split-bf16.
// Latency fixes vs R13: (1) only tid 0 polls the xch mbar, all other threads
// released via __syncthreads (no 640-thread single-address polling);
// (2) x_{t+1} prefetched via cp.async into smem, waited per-thread before
// gates (off critical path); (3) pusher warp does only the push.
// ---------------------------------------------------------------------------
#define A_OFF    0                          // [2 term][160 m][264 k] bf16
#define A_TERM   84480                      // 160*528
#define BT_OFF   168960                     // [2 par][2 term][8 n][264 k] bf16
#define BT_PAR   8448
#define BT_TERM  4224
#define STG_OFF  185856                     // [2 par][8 src][8 b][32 k] f32
#define ZB_OFF   202240                     // [2 kh][160 m][9] f32
#define XB_OFF   213760                     // [2 par][4 g][256] f32
#define HST_OFF  221952                     // [2 par][256] f32
#define MB_OFF   224000                     // xch mbar
#define R_SMEM_BYTES 224032

__global__ void __launch_bounds__(640, 1) __cluster_dims__(8, 1, 1)
recur_kernel(const float* __restrict__ Ui, const float* __restrict__ Uf,
             const float* __restrict__ Uc, const float* __restrict__ Uo,
             const float* __restrict__ Wmem, const float* __restrict__ Umem,
             float* __restrict__ out)
{
    extern __shared__ char smc[];
    const int bg   = blockIdx.x >> 3;
    const int sl   = blockIdx.x & 7;
    const int tid  = threadIdx.x;
    const int warp = tid >> 5;
    const int lane = tid & 31;

    const unsigned smb    = smu32(smc);
    const unsigned xch_mb = smb + MB_OFF;

    float* stg  = (float*)(smc + STG_OFF);
    float* zb   = (float*)(smc + ZB_OFF);
    float* xbf  = (float*)(smc + XB_OFF);
    float* hst  = (float*)(smc + HST_OFF);

    if (tid == 0) mb_init(xch_mb, 1);

    // ---- fill A (hi/lo bf16): gates then Cmem ----
    for (int idx = tid; idx < 32768; idx += 640) {
        int m = idx >> 8, k = idx & 255;
        int g = m >> 5;
        const float* W = (g == 0) ? Ui : (g == 1) ? Uf : (g == 2) ? Uc : Uo;
        float w = W[(size_t)k * U_ + sl * 32 + (m & 31)];
        __nv_bfloat16 h1 = __float2bfloat16(w);
        __nv_bfloat16 h2 = __float2bfloat16(w - __bfloat162float(h1));
        *(__nv_bfloat16*)(smc + A_OFF + m * 528 + k * 2) = h1;
        *(__nv_bfloat16*)(smc + A_OFF + A_TERM + m * 528 + k * 2) = h2;
    }
    for (int idx = tid; idx < 8192; idx += 640) {
        int c = idx >> 8, k = idx & 255;
        float s = 0.f;
#pragma unroll 8
        for (int m2 = 0; m2 < M_; m2++)
            s += Umem[k * M_ + m2] * Wmem[m2 * U_ + sl * 32 + c];
        float w = 0.1f * s;
        int m = 128 + c;
        __nv_bfloat16 h1 = __float2bfloat16(w);
        __nv_bfloat16 h2 = __float2bfloat16(w - __bfloat162float(h1));
        *(__nv_bfloat16*)(smc + A_OFF + m * 528 + k * 2) = h1;
        *(__nv_bfloat16*)(smc + A_OFF + A_TERM + m * 528 + k * 2) = h2;
    }
    for (int i = tid; i < 4096; i += 640) stg[i] = 0.f;     // h(-1) = 0

    // ---- x for t=0 via cp.async into xbf[0] (gate threads) ----
    const float* xgsrc = g_X + (size_t)bg * 8192 + sl * 1024 + tid;  // +g*256
    const unsigned xgdst = smb + XB_OFF + (unsigned)(tid * 4);       // +g*1024
    if (tid < 256) {
#pragma unroll
        for (int g = 0; g < 4; g++)
            CP_ASYNC4(xgdst + g * 1024, xgsrc + g * 256);
        CP_COMMIT();
    }

    // pusher (warp 19) peer addresses
    unsigned rd_base = 0, rm_peer = 0;
    if (warp == 19 && lane < 8) {
        asm("mapa.shared::cluster.u32 %0, %1, %2;" : "=r"(rd_base)
            : "r"(smb + STG_OFF + (unsigned)(sl * 1024)), "r"(lane));
        asm("mapa.shared::cluster.u32 %0, %1, %2;" : "=r"(rm_peer)
            : "r"(xch_mb), "r"(lane));
    }
    __syncthreads();

    // ---- load A fragments into registers (once) ----
    const int tau = warp >> 1;               // m-tile 0..9
    const int kh  = warp & 1;                // K-half
    const unsigned arow = (unsigned)((lane & 7) + ((lane >> 3) & 1) * 8);
    const unsigned acol = (unsigned)((lane >> 4) * 8);
    const unsigned aAddrH = smb + A_OFF + (tau * 16 + arow) * 528 +
                            (kh * 128 + acol) * 2;
    const unsigned aAddrL = aAddrH + A_TERM;
    unsigned aH[8][4], aL[8][4];
#pragma unroll
    for (int q = 0; q < 8; q++) {
        LDSM4(aH[q][0], aH[q][1], aH[q][2], aH[q][3], aAddrH + q * 32);
        LDSM4(aL[q][0], aL[q][1], aL[q][2], aL[q][3], aAddrL + q * 32);
    }

    // B ldmatrix lane base
    const unsigned l2   = (unsigned)(lane & 15);
    const unsigned bBase = smb + BT_OFF + (l2 & 7) * 528 +
                           (((l2 >> 3) & 1) * 8 + kh * 128) * 2;

    // gate-thread persistent state (tid < 256)
    const int gb  = tid >> 5;
    const int gcc = tid & 31;
    float creg = 0.f, rreg = 0.f;
    float* outp = out + ((size_t)(bg * 8 + gb) * T_) * U_ + sl * 32 + gcc;

    if (tid == 0) mb_expect_tx(xch_mb, 8192);    // phase 0 (consumed at t=1)
    __syncthreads();
    asm volatile("barrier.cluster.arrive.aligned;" ::: "memory");
    asm volatile("barrier.cluster.wait.aligned;" ::: "memory");

    for (int t = 0; t < T_; t++) {
        const int cur = t & 1, nxt = cur ^ 1;

        // ---- (a) prefetch x_{t+1} via cp.async (no regs, hidden) ----
        if (tid < 256 && t + 1 < T_) {
            const float* src = xgsrc + (size_t)(t + 1) * 131072;
            const unsigned dst = xgdst + (unsigned)(nxt * 4096);
#pragma unroll
            for (int g = 0; g < 4; g++)
                CP_ASYNC4(dst + g * 1024, src + g * 256);
            CP_COMMIT();
        }

        // ---- (b) h availability: SINGLE poller, HW-barrier release ----
        if (t > 0 && tid == 0) {
            mb_wait(xch_mb, (unsigned)((t - 1) & 1));
            mb_expect_tx(xch_mb, 8192);
        }
        __syncthreads();

        // ---- (c) build B tiles (bf16 hi/lo) from staged fp32 h ----
        if (tid < 512) {
            const float* sc = stg + cur * 2048;
            char* bt = smc + BT_OFF + cur * BT_PAR;
#pragma unroll
            for (int r = 0; r < 2; r++) {
                int w2 = tid * 2 + r;
                int b  = w2 >> 7;
                int k  = (w2 & 127) * 2;
                int q  = k >> 5, kk = k & 31;
                float v0 = sc[q * 256 + b * 32 + kk];
                float v1 = sc[q * 256 + b * 32 + kk + 1];
                __nv_bfloat16 h0 = __float2bfloat16(v0);
                __nv_bfloat16 l0 = __float2bfloat16(v0 - __bfloat162float(h0));
                __nv_bfloat16 h1 = __float2bfloat16(v1);
                __nv_bfloat16 l1 = __float2bfloat16(v1 - __bfloat162float(h1));
                unsigned hiw = (unsigned)__bfloat16_as_ushort(h0) |
                               ((unsigned)__bfloat16_as_ushort(h1) << 16);
                unsigned low = (unsigned)__bfloat16_as_ushort(l0) |
                               ((unsigned)__bfloat16_as_ushort(l1) << 16);
                *(unsigned*)(bt + b * 528 + k * 2)           = hiw;
                *(unsigned*)(bt + BT_TERM + b * 528 + k * 2) = low;
            }
        }
        __syncthreads();

        // ---- (d) MMA: 8 ksteps x 3 terms ----
        {
            float d0 = 0.f, d1 = 0.f, d2 = 0.f, d3 = 0.f;
            const unsigned bp = bBase + (unsigned)(cur * BT_PAR);
#pragma unroll
            for (int q = 0; q < 8; q++) {
                unsigned bh0, bh1, bl0, bl1;
                LDSM2(bh0, bh1, bp + q * 32);
                LDSM2(bl0, bl1, bp + BT_TERM + q * 32);
                MMA16816(d0, d1, d2, d3, aH[q][0], aH[q][1], aH[q][2],
                         aH[q][3], bh0, bh1);
                MMA16816(d0, d1, d2, d3, aH[q][0], aH[q][1], aH[q][2],
                         aH[q][3], bl0, bl1);
                MMA16816(d0, d1, d2, d3, aL[q][0], aL[q][1], aL[q][2],
                         aL[q][3], bh0, bh1);
            }
            const int m0 = tau * 16 + (lane >> 2);
            const int n0 = (lane & 3) * 2;
            float* zr_ = zb + kh * 1440;
            zr_[m0 * 9 + n0]           = d0;
            zr_[m0 * 9 + n0 + 1]       = d1;
            zr_[(m0 + 8) * 9 + n0]     = d2;
            zr_[(m0 + 8) * 9 + n0 + 1] = d3;
        }
        __syncthreads();

        // ---- (e) gates (warps 0-7) ; pusher = warp 19 ----
        if (tid < 256) {
            CP_WAIT1();                       // xbf[cur] complete
            const float* z0 = zb;
            const float* z1 = zb + 1440;
            float zi = z0[gcc * 9 + gb]         + z1[gcc * 9 + gb];
            float zf = z0[(32 + gcc) * 9 + gb]  + z1[(32 + gcc) * 9 + gb];
            float zc = z0[(64 + gcc) * 9 + gb]  + z1[(64 + gcc) * 9 + gb];
            float zo = z0[(96 + gcc) * 9 + gb]  + z1[(96 + gcc) * 9 + gb];
            float zr = z0[(128 + gcc) * 9 + gb] + z1[(128 + gcc) * 9 + gb];
            const float* xc = xbf + cur * 1024 + tid;
            float rn = rreg + zr;
            float pi  = xc[0]   + zi + rn;
            float pff = xc[256] + zf;
            float pc  = xc[512] + zc;
            float po  = xc[768] + zo;
            float ig = __fdividef(1.f, 1.f + __expf(-pi));
            float fg = __fdividef(1.f, 1.f + __expf(-pff));
            float ct = __fdividef(2.f, 1.f + __expf(-2.f * pc)) - 1.f;
            float og = __fdividef(1.f, 1.f + __expf(-po));
            float cn = fg * creg + ig * ct;
            float hv = og * (__fdividef(2.f, 1.f + __expf(-2.f * cn)) - 1.f);
            creg = cn;
            rreg = rn;
            hst[cur * 256 + tid] = hv;

            asm volatile("bar.sync 2, 288;" ::: "memory");
            outp[(size_t)t * U_] = hv;
        } else if (warp == 19) {
            asm volatile("bar.sync 2, 288;" ::: "memory");
            if (lane < 8 && t + 1 < T_) {
                asm volatile("fence.proxy.async.shared::cta;" ::: "memory");
                unsigned dst = rd_base + (unsigned)(nxt * 8192);
                unsigned src = smb + HST_OFF + (unsigned)(cur * 1024);
                asm volatile(
                    "cp.async.bulk.shared::cluster.shared::cta"
                    ".mbarrier::complete_tx::bytes [%0], [%1], %2, [%3];"
                    :: "r"(dst), "r"(src), "r"(1024u), "r"(rm_peer)
                    : "memory");
            }
        }
        // warps 8..18 loop to the top __syncthreads (HW barrier — no
        // polling). Dataflow safety: phase t completes only after ALL 8
        // CTAs' pushes; each CTA pushes after its own bar 2 => after all
        // of its zbuf/BT reads for step t.
    }

    asm volatile("barrier.cluster.arrive.aligned;" ::: "memory");
    asm volatile("barrier.cluster.wait.aligned;" ::: "memory");
}

// ---------------------------------------------------------------------------
// Launcher: capture-legal (exactly 2 kernel launches, default stream)
// ---------------------------------------------------------------------------
extern "C" void kernel_launch(void* const* d_in, const int* in_sizes, int n_in,
                              void* d_out, int out_size)
{
    const float* inp  = (const float*)d_in[0];
    const float* Wi   = (const float*)d_in[1];
    const float* Wf   = (const float*)d_in[2];
    const float* Wc   = (const float*)d_in[3];
    const float* Wo   = (const float*)d_in[4];
    const float* Uig  = (const float*)d_in[5];
    const float* Ufg  = (const float*)d_in[6];
    const float* Ucg  = (const float*)d_in[7];
    const float* Uog  = (const float*)d_in[8];
    const float* Wmem = (const float*)d_in[9];
    const float* Umem = (const float*)d_in[10];
    const float* bi   = (const float*)d_in[11];
    const float* bf   = (const float*)d_in[12];
    const float* bc   = (const float*)d_in[13];
    const float* bo   = (const float*)d_in[14];
    float* out = (float*)d_out;

    cudaFuncSetAttribute(proj_kernel,
                         cudaFuncAttributeMaxDynamicSharedMemorySize,
                         K1_SMEM_BYTES);
    proj_kernel<<<1024, 512, K1_SMEM_BYTES, 0>>>(inp, Wi, Wf, Wc, Wo,
                                                 bi, bf, bc, bo);

    cudaFuncSetAttribute(recur_kernel,
                         cudaFuncAttributeMaxDynamicSharedMemorySize,
                         R_SMEM_BYTES);
    recur_kernel<<<128, 640, R_SMEM_BYTES, 0>>>(Uig, Ufg, Ucg, Uog,
                                                Wmem, Umem, out);
}

// round 17
// speedup vs baseline: 1.7183x; 1.1222x over previous
#include <cuda_runtime.h>
#include <cuda_bf16.h>
#include <math.h>

#define B_ 128
#define T_ 1024
#define D_ 128
#define U_ 256
#define M_ 64

// Static device scratch (no cudaMalloc anywhere)
// Layout: [t][bg(16)][sl(8)][g(4)][b(8)][c(32)]  (CTA-contiguous blocks)
__device__ float g_X[134217728];

// ---------------------------------------------------------------------------
// helpers
// ---------------------------------------------------------------------------
__device__ __forceinline__ void fma2(unsigned long long& d,
                                     unsigned long long a,
                                     unsigned long long b) {
    asm("fma.rn.f32x2 %0, %1, %2, %0;" : "+l"(d) : "l"(a), "l"(b));
}
__device__ __forceinline__ float sum2(unsigned long long v) {
    return __uint_as_float((unsigned)v) + __uint_as_float((unsigned)(v >> 32));
}
__device__ __forceinline__ unsigned long long pk2(float a, float b) {
    unsigned long long r;
    asm("mov.b64 %0, {%1, %2};" : "=l"(r) : "f"(a), "f"(b));
    return r;
}
__device__ __forceinline__ unsigned smu32(const void* p) {
    return (unsigned)__cvta_generic_to_shared(p);
}
__device__ __forceinline__ void mb_init(unsigned mbar, unsigned count) {
    asm volatile("mbarrier.init.shared.b64 [%0], %1;"
                 :: "r"(mbar), "r"(count) : "memory");
}
__device__ __forceinline__ void mb_expect_tx(unsigned mbar, unsigned bytes) {
    asm volatile("mbarrier.arrive.expect_tx.shared.b64 _, [%0], %1;"
                 :: "r"(mbar), "r"(bytes) : "memory");
}
__device__ __forceinline__ void mb_wait(unsigned mbar, unsigned parity) {
    unsigned done;
    asm volatile(
        "{\n\t.reg .pred p;\n\t"
        "mbarrier.try_wait.parity.acquire.cta.shared::cta.b64 p, [%1], %2;\n\t"
        "selp.b32 %0, 1, 0, p;\n\t}"
        : "=r"(done) : "r"(mbar), "r"(parity) : "memory");
    while (!done) {
        asm volatile(
            "{\n\t.reg .pred p;\n\t"
            "mbarrier.try_wait.parity.acquire.cta.shared::cta.b64 p, [%1], %2, 0x989680;\n\t"
            "selp.b32 %0, 1, 0, p;\n\t}"
            : "=r"(done) : "r"(mbar), "r"(parity) : "memory");
    }
}
#define LDSM4(r0, r1, r2, r3, a) \
    asm volatile("ldmatrix.sync.aligned.m8n8.x4.shared.b16 {%0,%1,%2,%3}, [%4];" \
                 : "=r"(r0), "=r"(r1), "=r"(r2), "=r"(r3) : "r"(a))
#define LDSM2(r0, r1, a) \
    asm volatile("ldmatrix.sync.aligned.m8n8.x2.shared.b16 {%0,%1}, [%2];" \
                 : "=r"(r0), "=r"(r1) : "r"(a))
#define MMA16816(d0, d1, d2, d3, a0, a1, a2, a3, b0, b1) \
    asm volatile("mma.sync.aligned.m16n8k16.row.col.f32.bf16.bf16.f32 " \
                 "{%0,%1,%2,%3}, {%4,%5,%6,%7}, {%8,%9}, {%0,%1,%2,%3};" \
                 : "+f"(d0), "+f"(d1), "+f"(d2), "+f"(d3) \
                 : "r"(a0), "r"(a1), "r"(a2), "r"(a3), "r"(b0), "r"(b1))
#define CP_ASYNC4(dst, src) \
    asm volatile("cp.async.ca.shared.global [%0], [%1], 4;" \
                 :: "r"(dst), "l"(src) : "memory")
#define CP_COMMIT() asm volatile("cp.async.commit_group;" ::: "memory")
#define CP_WAIT2()  asm volatile("cp.async.wait_group 2;" ::: "memory")

// ---------------------------------------------------------------------------
// K1: input projections (R11 version — known-good)
// ---------------------------------------------------------------------------
#define P_ISH_STR 130
#define P_WSH_STR 68
#define P_WSH_OFF (128 * P_ISH_STR)
#define P_WBUF    (128 * P_WSH_STR)
#define K1_SMEM_BYTES ((128 * P_ISH_STR + 2 * P_WBUF) * 4)

__global__ void __launch_bounds__(512) proj_kernel(
    const float* __restrict__ inp,
    const float* __restrict__ Wi, const float* __restrict__ Wf,
    const float* __restrict__ Wc, const float* __restrict__ Wo,
    const float* __restrict__ bi, const float* __restrict__ bf,
    const float* __restrict__ bc, const float* __restrict__ bo)
{
    extern __shared__ float sm[];
    float* Ish = sm;
    float* Wsh = sm + P_WSH_OFF;

    const int t   = blockIdx.x;
    const int tid = threadIdx.x;

    const float* Wmat[4] = { Wi, Wf, Wc, Wo };
    const float* bvec[4] = { bi, bf, bc, bo };

    for (int i = tid; i < 128 * 128; i += 512) {
        int b = i >> 7, d = i & 127;
        Ish[b * P_ISH_STR + d] = inp[((size_t)b * T_ + t) * D_ + d];
    }
    {
        const float* W = Wmat[0];
#pragma unroll
        for (int k = 0; k < 4; k++) {
            int fi = tid + 512 * k;
            int d  = fi >> 4, u4 = fi & 15;
            *(float4*)&Wsh[d * P_WSH_STR + u4 * 4] =
                *(const float4*)&W[(size_t)d * U_ + u4 * 4];
        }
    }
    __syncthreads();

    const int j4 = (tid & 15) * 4;
    const int b4 = (tid >> 4) * 4;

    for (int tl = 0; tl < 16; tl++) {
        const int g  = tl >> 2;
        const int u0 = (tl & 3) * 64;
        float* Wcur = Wsh + (tl & 1) * P_WBUF;

        float4 wpre[4];
        if (tl + 1 < 16) {
            const float* W = Wmat[(tl + 1) >> 2];
            const int nu0 = ((tl + 1) & 3) * 64;
#pragma unroll
            for (int k = 0; k < 4; k++) {
                int fi = tid + 512 * k;
                int d  = fi >> 4, u4 = fi & 15;
                wpre[k] = *(const float4*)&W[(size_t)d * U_ + nu0 + u4 * 4];
            }
        }

        unsigned long long acc[4][4];
#pragma unroll
        for (int jj = 0; jj < 4; jj++)
#pragma unroll
            for (int bb = 0; bb < 4; bb++) acc[jj][bb] = 0ull;

#pragma unroll 8
        for (int d = 0; d < 128; d += 2) {
            float4 wa = *(const float4*)&Wcur[d * P_WSH_STR + j4];
            float4 wb = *(const float4*)&Wcur[(d + 1) * P_WSH_STR + j4];
            unsigned long long w0 = pk2(wa.x, wb.x), w1 = pk2(wa.y, wb.y);
            unsigned long long w2 = pk2(wa.z, wb.z), w3 = pk2(wa.w, wb.w);
#pragma unroll
            for (int bb = 0; bb < 4; bb++) {
                unsigned long long iv = *(const unsigned long long*)
                    &Ish[(b4 + bb) * P_ISH_STR + d];
                fma2(acc[0][bb], w0, iv);
                fma2(acc[1][bb], w1, iv);
                fma2(acc[2][bb], w2, iv);
                fma2(acc[3][bb], w3, iv);
            }
        }

        const int u   = u0 + j4;
        const int slo = u >> 5;
        const int co  = u & 31;
        const float bv0 = bvec[g][u + 0], bv1 = bvec[g][u + 1];
        const float bv2 = bvec[g][u + 2], bv3 = bvec[g][u + 3];
#pragma unroll
        for (int bb = 0; bb < 4; bb++) {
            int bfull = b4 + bb;
            float* p = g_X + (size_t)t * 131072 + (size_t)(bfull >> 3) * 8192 +
                       slo * 1024 + g * 256 + (bfull & 7) * 32 + co;
            *(float4*)p = make_float4(sum2(acc[0][bb]) + bv0,
                                      sum2(acc[1][bb]) + bv1,
                                      sum2(acc[2][bb]) + bv2,
                                      sum2(acc[3][bb]) + bv3);
        }

        if (tl + 1 < 16) {
            float* Wnxt = Wsh + ((tl + 1) & 1) * P_WBUF;
#pragma unroll
            for (int k = 0; k < 4; k++) {
                int fi = tid + 512 * k;
                int d  = fi >> 4, u4 = fi & 15;
                *(float4*)&Wnxt[d * P_WSH_STR + u4 * 4] = wpre[k];
            }
            __syncthreads();
        }
    }
}

// ---------------------------------------------------------------------------
// K2: persistent recurrence, cluster-8, grid 64, 640 threads, HMMA.
// TWO interleaved independent streams per cluster (R15 design), with the
// mbar-corruption bug fixed: mbarriers live in the aliased region, so they
// are initialized AFTER the A-staging region's last use (post-LDSM), by the
// sole poller thread (tid 0), before any expect/push (cluster barrier
// orders visibility to peers).
// ---------------------------------------------------------------------------
#define A_OFF    0
#define A_TERM   84480                       // 160*528
// dynamic buffers (alias into A region after fragment load):
#define BT_OFF2  0                           // [s][par][term][8 n][528B]
#define BT_S     16896
#define BT_PAR   8448
#define BT_TERM  4224
#define STG_OFF2 33792                       // [s][par][8 src][8 b][32 k] f32
#define STG_S    16384
#define ZB_OFF2  66560                       // [s][2 kh][160 m][9] f32
#define ZB_S     11520
#define XB_OFF2  89600                       // [s][par][4 g][256] f32
#define XB_S     8192
#define HST_OFF2 105984                      // [s][par][256] f32
#define HST_S    2048
#define MB_OFF2  110080                      // 2 mbars (init AFTER A reuse!)
#define R_SMEM_BYTES 169024

__global__ void __launch_bounds__(640, 1) __cluster_dims__(8, 1, 1)
recur_kernel(const float* __restrict__ Ui, const float* __restrict__ Uf,
             const float* __restrict__ Uc, const float* __restrict__ Uo,
             const float* __restrict__ Wmem, const float* __restrict__ Umem,
             float* __restrict__ out)
{
    extern __shared__ char smc[];
    const int cid  = blockIdx.x >> 3;        // cluster 0..7
    const int sl   = blockIdx.x & 7;
    const int bgA  = cid * 2;                // stream 0 batch group
    const int tid  = threadIdx.x;
    const int warp = tid >> 5;
    const int lane = tid & 31;

    const unsigned smb    = smu32(smc);
    const unsigned xch_mb = smb + MB_OFF2;   // +s*8

    // ---- fill A (hi/lo bf16): gates then Cmem (staging; freed after LDSM) --
    for (int idx = tid; idx < 32768; idx += 640) {
        int m = idx >> 8, k = idx & 255;
        int g = m >> 5;
        const float* W = (g == 0) ? Ui : (g == 1) ? Uf : (g == 2) ? Uc : Uo;
        float w = W[(size_t)k * U_ + sl * 32 + (m & 31)];
        __nv_bfloat16 h1 = __float2bfloat16(w);
        __nv_bfloat16 h2 = __float2bfloat16(w - __bfloat162float(h1));
        *(__nv_bfloat16*)(smc + A_OFF + m * 528 + k * 2) = h1;
        *(__nv_bfloat16*)(smc + A_OFF + A_TERM + m * 528 + k * 2) = h2;
    }
    for (int idx = tid; idx < 8192; idx += 640) {
        int c = idx >> 8, k = idx & 255;
        float s = 0.f;
#pragma unroll 8
        for (int m2 = 0; m2 < M_; m2++)
            s += Umem[k * M_ + m2] * Wmem[m2 * U_ + sl * 32 + c];
        float w = 0.1f * s;
        int m = 128 + c;
        __nv_bfloat16 h1 = __float2bfloat16(w);
        __nv_bfloat16 h2 = __float2bfloat16(w - __bfloat162float(h1));
        *(__nv_bfloat16*)(smc + A_OFF + m * 528 + k * 2) = h1;
        *(__nv_bfloat16*)(smc + A_OFF + A_TERM + m * 528 + k * 2) = h2;
    }
    __syncthreads();

    // ---- load A fragments into registers (once) ----
    const int tau = warp >> 1;               // m-tile 0..9
    const int kh  = warp & 1;                // K-half
    const unsigned arow = (unsigned)((lane & 7) + ((lane >> 3) & 1) * 8);
    const unsigned acol = (unsigned)((lane >> 4) * 8);
    const unsigned aAddrH = smb + A_OFF + (tau * 16 + arow) * 528 +
                            (kh * 128 + acol) * 2;
    const unsigned aAddrL = aAddrH + A_TERM;
    unsigned aH[8][4], aL[8][4];
#pragma unroll
    for (int q = 0; q < 8; q++) {
        LDSM4(aH[q][0], aH[q][1], aH[q][2], aH[q][3], aAddrH + q * 32);
        LDSM4(aL[q][0], aL[q][1], aL[q][2], aL[q][3], aAddrL + q * 32);
    }
    __syncthreads();                         // A region now reusable

    // ---- mbarriers: init AFTER the aliased region's last A use ----
    if (tid == 0) {
        mb_init(xch_mb, 1);
        mb_init(xch_mb + 8, 1);
    }

    // ---- init dynamic buffers (alias region) ----
    {
        float* stg = (float*)(smc + STG_OFF2);
        for (int i = tid; i < 8192; i += 640) stg[i] = 0.f;   // h(-1)=0 both s
    }

    // ---- x for t=0 via cp.async, both streams (2 commit groups) ----
    const float* xgsrc = g_X + (size_t)bgA * 8192 + sl * 1024 + tid; // +s*8192
    const unsigned xgdst = smb + XB_OFF2 + (unsigned)(tid * 4);      // +s*XB_S
    if (tid < 256) {
#pragma unroll
        for (int g = 0; g < 4; g++)
            CP_ASYNC4(xgdst + g * 1024, xgsrc + g * 256);
        CP_COMMIT();
#pragma unroll
        for (int g = 0; g < 4; g++)
            CP_ASYNC4(xgdst + XB_S + g * 1024, xgsrc + 8192 + g * 256);
        CP_COMMIT();
    } else {
        CP_COMMIT(); CP_COMMIT();            // keep group counts uniform
    }

    // pusher (warp 19) peer addresses
    unsigned rd_base = 0, rm_base = 0;
    if (warp == 19 && lane < 8) {
        asm("mapa.shared::cluster.u32 %0, %1, %2;" : "=r"(rd_base)
            : "r"(smb + STG_OFF2 + (unsigned)(sl * 1024)), "r"(lane));
        asm("mapa.shared::cluster.u32 %0, %1, %2;" : "=r"(rm_base)
            : "r"(xch_mb), "r"(lane));
    }

    // B ldmatrix lane base (per warp K-half)
    const unsigned l2   = (unsigned)(lane & 15);
    const unsigned bBase = smb + BT_OFF2 + (l2 & 7) * 528 +
                           (((l2 >> 3) & 1) * 8 + kh * 128) * 2;

    // gate-thread persistent state (tid < 256): two streams
    const int gb  = tid >> 5;
    const int gcc = tid & 31;
    float creg[2] = {0.f, 0.f}, rreg[2] = {0.f, 0.f};
    float* outp = out + ((size_t)(bgA * 8 + gb) * T_) * U_ + sl * 32 + gcc;

    if (tid == 0) {                          // phase 0 expects (same thread
        mb_expect_tx(xch_mb, 8192);          //  as init: program order)
        mb_expect_tx(xch_mb + 8, 8192);
    }
    __syncthreads();
    asm volatile("barrier.cluster.arrive.aligned;" ::: "memory");
    asm volatile("barrier.cluster.wait.aligned;" ::: "memory");

    for (int t = 0; t < T_; t++) {
        const int cur = t & 1, nxt = cur ^ 1;
#pragma unroll
        for (int s = 0; s < 2; s++) {
            const unsigned sBT  = (unsigned)(s * BT_S);
            const unsigned sSTG = (unsigned)(s * STG_S);
            const unsigned mbS  = xch_mb + (unsigned)(s * 8);

            // (a) prefetch x_{t+1} for this stream
            if (tid < 256 && t + 1 < T_) {
                const float* src = xgsrc + s * 8192 + (size_t)(t + 1) * 131072;
                const unsigned dst = xgdst + (unsigned)(s * XB_S + nxt * 4096);
#pragma unroll
                for (int g = 0; g < 4; g++)
                    CP_ASYNC4(dst + g * 1024, src + g * 256);
            }
            CP_COMMIT();

            // (b) h availability: single poller, HW-barrier release
            if (t > 0 && tid == 0) {
                mb_wait(mbS, (unsigned)((t - 1) & 1));
                mb_expect_tx(mbS, 8192);
            }
            __syncthreads();

            // (c) build B tiles (bf16 hi/lo) from staged fp32 h
            if (tid < 512) {
                const float* sc = (const float*)(smc + STG_OFF2 + sSTG) +
                                  cur * 2048;
                char* bt = smc + BT_OFF2 + sBT + cur * BT_PAR;
#pragma unroll
                for (int r = 0; r < 2; r++) {
                    int w2 = tid * 2 + r;
                    int b  = w2 >> 7;
                    int k  = (w2 & 127) * 2;
                    int q  = k >> 5, kk = k & 31;
                    float v0 = sc[q * 256 + b * 32 + kk];
                    float v1 = sc[q * 256 + b * 32 + kk + 1];
                    __nv_bfloat16 h0 = __float2bfloat16(v0);
                    __nv_bfloat16 l0 =
                        __float2bfloat16(v0 - __bfloat162float(h0));
                    __nv_bfloat16 h1 = __float2bfloat16(v1);
                    __nv_bfloat16 l1 =
                        __float2bfloat16(v1 - __bfloat162float(h1));
                    unsigned hiw = (unsigned)__bfloat16_as_ushort(h0) |
                                   ((unsigned)__bfloat16_as_ushort(h1) << 16);
                    unsigned low = (unsigned)__bfloat16_as_ushort(l0) |
                                   ((unsigned)__bfloat16_as_ushort(l1) << 16);
                    *(unsigned*)(bt + b * 528 + k * 2)           = hiw;
                    *(unsigned*)(bt + BT_TERM + b * 528 + k * 2) = low;
                }
            }
            __syncthreads();

            // (d) MMA: 8 ksteps x 3 terms (all 20 warps are MMA workers)
            {
                float d0 = 0.f, d1 = 0.f, d2 = 0.f, d3 = 0.f;
                const unsigned bp = bBase + sBT + (unsigned)(cur * BT_PAR);
#pragma unroll
                for (int q = 0; q < 8; q++) {
                    unsigned bh0, bh1, bl0, bl1;
                    LDSM2(bh0, bh1, bp + q * 32);
                    LDSM2(bl0, bl1, bp + BT_TERM + q * 32);
                    MMA16816(d0, d1, d2, d3, aH[q][0], aH[q][1], aH[q][2],
                             aH[q][3], bh0, bh1);
                    MMA16816(d0, d1, d2, d3, aH[q][0], aH[q][1], aH[q][2],
                             aH[q][3], bl0, bl1);
                    MMA16816(d0, d1, d2, d3, aL[q][0], aL[q][1], aL[q][2],
                             aL[q][3], bh0, bh1);
                }
                const int m0 = tau * 16 + (lane >> 2);
                const int n0 = (lane & 3) * 2;
                float* zr_ = (float*)(smc + ZB_OFF2 + s * ZB_S) + kh * 1440;
                zr_[m0 * 9 + n0]           = d0;
                zr_[m0 * 9 + n0 + 1]       = d1;
                zr_[(m0 + 8) * 9 + n0]     = d2;
                zr_[(m0 + 8) * 9 + n0 + 1] = d3;
            }
            __syncthreads();

            // (e) gates (warps 0-7) ; pusher = warp 19
            if (tid < 256) {
                CP_WAIT2();                   // x[s][cur] complete
                const float* z0 = (const float*)(smc + ZB_OFF2 + s * ZB_S);
                const float* z1 = z0 + 1440;
                float zi = z0[gcc * 9 + gb]         + z1[gcc * 9 + gb];
                float zf = z0[(32 + gcc) * 9 + gb]  + z1[(32 + gcc) * 9 + gb];
                float zc = z0[(64 + gcc) * 9 + gb]  + z1[(64 + gcc) * 9 + gb];
                float zo = z0[(96 + gcc) * 9 + gb]  + z1[(96 + gcc) * 9 + gb];
                float zr = z0[(128 + gcc) * 9 + gb] + z1[(128 + gcc) * 9 + gb];
                const float* xc = (const float*)(smc + XB_OFF2 + s * XB_S) +
                                  cur * 1024 + tid;
                float rn = rreg[s] + zr;
                float pi  = xc[0]   + zi + rn;
                float pff = xc[256] + zf;
                float pc  = xc[512] + zc;
                float po  = xc[768] + zo;
                float ig = __fdividef(1.f, 1.f + __expf(-pi));
                float fg = __fdividef(1.f, 1.f + __expf(-pff));
                float ct = __fdividef(2.f, 1.f + __expf(-2.f * pc)) - 1.f;
                float og = __fdividef(1.f, 1.f + __expf(-po));
                float cn = fg * creg[s] + ig * ct;
                float hv = og *
                    (__fdividef(2.f, 1.f + __expf(-2.f * cn)) - 1.f);
                creg[s] = cn;
                rreg[s] = rn;
                ((float*)(smc + HST_OFF2 + s * HST_S))[cur * 256 + tid] = hv;

                asm volatile("bar.sync 2, 288;" ::: "memory");
                outp[(size_t)t * U_ + (size_t)s * 2097152] = hv;
            } else if (warp == 19) {
                asm volatile("bar.sync 2, 288;" ::: "memory");
                if (lane < 8 && t + 1 < T_) {
                    asm volatile("fence.proxy.async.shared::cta;"
                                 ::: "memory");
                    unsigned dst = rd_base + sSTG + (unsigned)(nxt * 8192);
                    unsigned src = smb + HST_OFF2 + (unsigned)s * HST_S +
                                   (unsigned)(cur * 1024);
                    asm volatile(
                        "cp.async.bulk.shared::cluster.shared::cta"
                        ".mbarrier::complete_tx::bytes [%0], [%1], %2, [%3];"
                        :: "r"(dst), "r"(src), "r"(1024u),
                           "r"(rm_base + (unsigned)(s * 8))
                        : "memory");
                }
            }
            // warps 8..18 flow to the next stream's __syncthreads (HW
            // barrier, no polling). Per-stream dataflow safety identical
            // to R14: phase t of stream s completes only after all 8 CTAs'
            // stream-s pushes, each issued after that CTA's bar 2 for s
            // => after all of its zbuf/BT/stg reads for (s, t).
        }
    }

    asm volatile("barrier.cluster.arrive.aligned;" ::: "memory");
    asm volatile("barrier.cluster.wait.aligned;" ::: "memory");
}

// ---------------------------------------------------------------------------
// Launcher: capture-legal (exactly 2 kernel launches, default stream)
// ---------------------------------------------------------------------------
extern "C" void kernel_launch(void* const* d_in, const int* in_sizes, int n_in,
                              void* d_out, int out_size)
{
    const float* inp  = (const float*)d_in[0];
    const float* Wi   = (const float*)d_in[1];
    const float* Wf   = (const float*)d_in[2];
    const float* Wc   = (const float*)d_in[3];
    const float* Wo   = (const float*)d_in[4];
    const float* Uig  = (const float*)d_in[5];
    const float* Ufg  = (const float*)d_in[6];
    const float* Ucg  = (const float*)d_in[7];
    const float* Uog  = (const float*)d_in[8];
    const float* Wmem = (const float*)d_in[9];
    const float* Umem = (const float*)d_in[10];
    const float* bi   = (const float*)d_in[11];
    const float* bf   = (const float*)d_in[12];
    const float* bc   = (const float*)d_in[13];
    const float* bo   = (const float*)d_in[14];
    float* out = (float*)d_out;

    cudaFuncSetAttribute(proj_kernel,
                         cudaFuncAttributeMaxDynamicSharedMemorySize,
                         K1_SMEM_BYTES);
    proj_kernel<<<1024, 512, K1_SMEM_BYTES, 0>>>(inp, Wi, Wf, Wc, Wo,
                                                 bi, bf, bc, bo);

    cudaFuncSetAttribute(recur_kernel,
                         cudaFuncAttributeMaxDynamicSharedMemorySize,
                         R_SMEM_BYTES);
    recur_kernel<<<64, 640, R_SMEM_BYTES, 0>>>(Uig, Ufg, Ucg, Uog,
                                               Wmem, Umem, out);
}